// round 3
// baseline (speedup 1.0000x reference)
#include <cuda_runtime.h>

// ---------------------------------------------------------------------------
// Algebraic collapse of the reference:
//   beta[b,s,h] = dot(S[b,s,h*64:(h+1)*64], g_W[b,h,:]) + g_C[b,h]
//   out[b,s,h*64+e] = g_RV[b,h,e] * beta * (S_mas[b,s] != 0)
// where g_W[b,h,d] = sum_e WQ_w[e,d] * R_K[b,h,e],
//       g_C[b,h]   = sum_e WQ_b[e]   * R_K[b,h,e],
//       R_K[b,h,e] = WK_b[e] + sum_d R[b,h*64+d]*WK_w[e,d]
//       g_RV[b,h,e]= WV_b[e] + sum_d R[b,h*64+d]*WV_w[e,d]
// HBM-bound streaming problem: 512 MB traffic -> ~64 us floor on GB300.
// ---------------------------------------------------------------------------

#define MAX_DPS 64

__device__ float g_W [MAX_DPS * 1024];
__device__ float g_RV[MAX_DPS * 1024];
__device__ float g_C [MAX_DPS * 16];

// ---------------------------------------------------------------------------
// Kernel 1: per-(batch, head) precompute. grid (dps, 16), block 64.
// ---------------------------------------------------------------------------
__global__ void precompute_kernel(const float* __restrict__ R,
                                  const float* __restrict__ WQ_w,
                                  const float* __restrict__ WQ_b,
                                  const float* __restrict__ WK_w,
                                  const float* __restrict__ WK_b,
                                  const float* __restrict__ WV_w,
                                  const float* __restrict__ WV_b) {
    const int b = blockIdx.x;
    const int h = blockIdx.y;
    const int e = threadIdx.x;  // 0..63

    __shared__ float r_s[64];
    __shared__ float rk_s[64];

    r_s[e] = R[b * 1024 + h * 64 + e];
    __syncthreads();

    // R_K[e], R_V[e]
    float rk = WK_b[e];
    float rv = WV_b[e];
#pragma unroll 8
    for (int d = 0; d < 64; d++) {
        float rd = r_s[d];
        rk = fmaf(rd, WK_w[e * 64 + d], rk);
        rv = fmaf(rd, WV_w[e * 64 + d], rv);
    }
    rk_s[e] = rk;
    g_RV[b * 1024 + h * 64 + e] = rv;
    __syncthreads();

    // W[d] = sum_e WQ_w[e,d] * R_K[e]   (thread index reinterpreted as d)
    const int d = e;
    float w = 0.0f;
#pragma unroll 8
    for (int ee = 0; ee < 64; ee++)
        w = fmaf(WQ_w[ee * 64 + d], rk_s[ee], w);
    g_W[b * 1024 + h * 64 + d] = w;

    if (e == 0) {
        float c = 0.0f;
        for (int ee = 0; ee < 64; ee++)
            c = fmaf(WQ_b[ee], rk_s[ee], c);
        g_C[b * 16 + h] = c;
    }
}

// ---------------------------------------------------------------------------
// Kernel 2: streaming pass. grid (dps, ceil(seq/ROWS)), block 256.
// Each thread owns one float4 slice of the 1024-wide row; a head is 16
// aligned lanes; dot-product reduced with shfl.xor width=16.
// ---------------------------------------------------------------------------
template <int ROWS_PER_BLOCK, int UNROLL>
__global__ __launch_bounds__(256) void stream_kernel(
    const float* __restrict__ S,
    const int*   __restrict__ S_mas,
    float*       __restrict__ out,
    int seq) {
    const int b   = blockIdx.x;
    const int tid = threadIdx.x;      // 0..255
    const int h   = tid >> 4;         // head = 16 consecutive lanes

    // Per-thread constants for the whole block: live in registers.
    const float4 w  = reinterpret_cast<const float4*>(g_W  + b * 1024)[tid];
    const float4 rv = reinterpret_cast<const float4*>(g_RV + b * 1024)[tid];
    const float  c  = g_C[b * 16 + h];

    const int row0 = blockIdx.y * ROWS_PER_BLOCK;
    const float4* Sp = reinterpret_cast<const float4*>(S) + (size_t)b * seq * 256;
    float4*       Op = reinterpret_cast<float4*>(out)     + (size_t)b * seq * 256;
    const int*    mp = S_mas + (size_t)b * seq;

    const int row_end = (row0 + ROWS_PER_BLOCK < seq) ? row0 + ROWS_PER_BLOCK : seq;

    int r = row0;
    // Fast path: full UNROLL batches.
    for (; r + UNROLL <= row_end; r += UNROLL) {
        float4 s[UNROLL];
        int    m[UNROLL];
#pragma unroll
        for (int u = 0; u < UNROLL; u++) {
            s[u] = Sp[(size_t)(r + u) * 256 + tid];
            m[u] = mp[r + u];
        }
#pragma unroll
        for (int u = 0; u < UNROLL; u++) {
            float p = s[u].x * w.x + s[u].y * w.y + s[u].z * w.z + s[u].w * w.w;
            p += __shfl_xor_sync(0xffffffffu, p, 8, 16);
            p += __shfl_xor_sync(0xffffffffu, p, 4, 16);
            p += __shfl_xor_sync(0xffffffffu, p, 2, 16);
            p += __shfl_xor_sync(0xffffffffu, p, 1, 16);
            const float beta = (p + c) * (m[u] != 0 ? 1.0f : 0.0f);
            float4 o;
            o.x = rv.x * beta;
            o.y = rv.y * beta;
            o.z = rv.z * beta;
            o.w = rv.w * beta;
            Op[(size_t)(r + u) * 256 + tid] = o;
        }
    }
    // Tail (only if seq % ROWS_PER_BLOCK != 0).
    for (; r < row_end; r++) {
        float4 s = Sp[(size_t)r * 256 + tid];
        int    m = mp[r];
        float p = s.x * w.x + s.y * w.y + s.z * w.z + s.w * w.w;
        p += __shfl_xor_sync(0xffffffffu, p, 8, 16);
        p += __shfl_xor_sync(0xffffffffu, p, 4, 16);
        p += __shfl_xor_sync(0xffffffffu, p, 2, 16);
        p += __shfl_xor_sync(0xffffffffu, p, 1, 16);
        const float beta = (p + c) * (m != 0 ? 1.0f : 0.0f);
        float4 o;
        o.x = rv.x * beta;
        o.y = rv.y * beta;
        o.z = rv.z * beta;
        o.w = rv.w * beta;
        Op[(size_t)r * 256 + tid] = o;
    }
}

// ---------------------------------------------------------------------------
// Launch
// Inputs (metadata order):
//   0 S (dps,seq,1024) f32   1 R (dps,1,1024) f32
//   2 S_mas (dps,seq,1) i32  3 R_mas (dps,1,1) i32 (dead)
//   4 WQ_w  5 WQ_b  6 WK_w  7 WK_b  8 WV_w  9 WV_b
// ---------------------------------------------------------------------------
extern "C" void kernel_launch(void* const* d_in, const int* in_sizes, int n_in,
                              void* d_out, int out_size) {
    const float* S     = (const float*)d_in[0];
    const float* R     = (const float*)d_in[1];
    const int*   S_mas = (const int*)  d_in[2];
    const float* WQ_w  = (const float*)d_in[4];
    const float* WQ_b  = (const float*)d_in[5];
    const float* WK_w  = (const float*)d_in[6];
    const float* WK_b  = (const float*)d_in[7];
    const float* WV_w  = (const float*)d_in[8];
    const float* WV_b  = (const float*)d_in[9];
    float* out = (float*)d_out;

    int dps = in_sizes[1] / 1024;          // R element count = dps*1024
    if (dps > MAX_DPS) dps = MAX_DPS;
    int seq = in_sizes[0] / (dps * 1024);  // S element count = dps*seq*1024

    precompute_kernel<<<dim3(dps, 16), 64>>>(R, WQ_w, WQ_b, WK_w, WK_b, WV_w, WV_b);

    constexpr int ROWS   = 64;
    constexpr int UNROLL = 4;
    int nblk = (seq + ROWS - 1) / ROWS;
    stream_kernel<ROWS, UNROLL><<<dim3(dps, nblk), 256>>>(S, S_mas, out, seq);
}

// round 5
// speedup vs baseline: 1.0844x; 1.0844x over previous
#include <cuda_runtime.h>

// ---------------------------------------------------------------------------
// Algebraic collapse of the reference:
//   beta[b,s,h] = dot(S[b,s,h*64:(h+1)*64], g_W[b,h,:]) + g_C[b,h]
//   out[b,s,h*64+e] = g_RV[b,h,e] * beta * (S_mas[b,s] != 0)
// where g_W[b,h,d] = sum_e WQ_w[e,d] * R_K[b,h,e],
//       g_C[b,h]   = sum_e WQ_b[e]   * R_K[b,h,e],
//       R_K[b,h,e] = WK_b[e] + sum_d R[b,h*64+d]*WK_w[e,d]
//       g_RV[b,h,e]= WV_b[e] + sum_d R[b,h*64+d]*WV_w[e,d]
// HBM-bound streaming: 512 MB traffic -> ~64 us floor on GB300.
// ---------------------------------------------------------------------------

#define MAX_DPS 64

__device__ float g_W [MAX_DPS * 1024];
__device__ float g_RV[MAX_DPS * 1024];
__device__ float g_C [MAX_DPS * 16];

// ---------------------------------------------------------------------------
// Kernel 1: per-batch precompute. grid (dps), block 256.
// Weights staged in smem with +1 row padding -> conflict-free LDS.
// Thread t handles pairs p = i*256 + t, i=0..3; h = p>>6 is WARP-UNIFORM
// (t>>6 constant per warp), so r_s[h*64+d] / rk_s[h*64+e] are broadcasts.
// ---------------------------------------------------------------------------
__global__ __launch_bounds__(256) void precompute_kernel(
    const float* __restrict__ R,
    const float* __restrict__ WQ_w,
    const float* __restrict__ WQ_b,
    const float* __restrict__ WK_w,
    const float* __restrict__ WK_b,
    const float* __restrict__ WV_w,
    const float* __restrict__ WV_b) {
    const int b = blockIdx.x;
    const int t = threadIdx.x;  // 0..255

    __shared__ float WS[64 * 65];   // padded weight tile
    __shared__ float r_s[1024];
    __shared__ float rk_s[1024];

    // Stage R row (coalesced).
#pragma unroll
    for (int i = 0; i < 4; i++)
        r_s[i * 256 + t] = R[b * 1024 + i * 256 + t];

    // ---- Phase A: R_K  (needs WK_w) ----
#pragma unroll
    for (int i = 0; i < 16; i++) {
        int idx = i * 256 + t;                 // 0..4095 coalesced
        WS[(idx >> 6) * 65 + (idx & 63)] = WK_w[idx];
    }
    __syncthreads();
#pragma unroll
    for (int i = 0; i < 4; i++) {
        const int p = i * 256 + t;
        const int h = p >> 6;                  // warp-uniform
        const int e = p & 63;
        float rk = WK_b[e];
#pragma unroll 8
        for (int d = 0; d < 64; d++)
            rk = fmaf(r_s[h * 64 + d], WS[e * 65 + d], rk);
        rk_s[p] = rk;
    }
    __syncthreads();

    // ---- Phase B: R_V  (needs WV_w) ----
#pragma unroll
    for (int i = 0; i < 16; i++) {
        int idx = i * 256 + t;
        WS[(idx >> 6) * 65 + (idx & 63)] = WV_w[idx];
    }
    __syncthreads();
#pragma unroll
    for (int i = 0; i < 4; i++) {
        const int p = i * 256 + t;
        const int h = p >> 6;
        const int e = p & 63;
        float rv = WV_b[e];
#pragma unroll 8
        for (int d = 0; d < 64; d++)
            rv = fmaf(r_s[h * 64 + d], WS[e * 65 + d], rv);
        g_RV[b * 1024 + p] = rv;               // coalesced
    }
    __syncthreads();

    // ---- Phase C: W[d] = sum_e WQ_w[e,d]*R_K[e]  (needs WQ_w) ----
#pragma unroll
    for (int i = 0; i < 16; i++) {
        int idx = i * 256 + t;
        WS[(idx >> 6) * 65 + (idx & 63)] = WQ_w[idx];
    }
    __syncthreads();
#pragma unroll
    for (int i = 0; i < 4; i++) {
        const int p = i * 256 + t;
        const int h = p >> 6;                  // warp-uniform
        const int d = p & 63;
        float w = 0.0f;
#pragma unroll 8
        for (int e = 0; e < 64; e++)
            w = fmaf(WS[e * 65 + d], rk_s[h * 64 + e], w);
        g_W[b * 1024 + p] = w;                 // coalesced
    }

    // c[h] = sum_e WQ_b[e]*R_K[h,e]  — 16 threads, one head each.
    if (t < 16) {
        float c = 0.0f;
#pragma unroll 8
        for (int e = 0; e < 64; e++)
            c = fmaf(WQ_b[e], rk_s[t * 64 + e], c);
        g_C[b * 16 + t] = c;
    }
}

// ---------------------------------------------------------------------------
// Kernel 2: streaming pass. grid (dps, ceil(seq/ROWS)), block 256.
// Thread owns one float4 slice of the 1024-wide row; head = 16 lanes;
// dot reduced with shfl.xor width=16. S read-once via __ldcs, out
// write-once via __stcs (evict-first: keep the two streams out of L2's way).
// ---------------------------------------------------------------------------
template <int ROWS_PER_BLOCK, int UNROLL>
__global__ __launch_bounds__(256) void stream_kernel(
    const float* __restrict__ S,
    const int*   __restrict__ S_mas,
    float*       __restrict__ out,
    int seq) {
    const int b   = blockIdx.x;
    const int tid = threadIdx.x;      // 0..255
    const int h   = tid >> 4;         // head = 16 consecutive lanes

    const float4 w  = reinterpret_cast<const float4*>(g_W  + b * 1024)[tid];
    const float4 rv = reinterpret_cast<const float4*>(g_RV + b * 1024)[tid];
    const float  c  = g_C[b * 16 + h];

    const int row0 = blockIdx.y * ROWS_PER_BLOCK;
    const float4* Sp = reinterpret_cast<const float4*>(S) + (size_t)b * seq * 256;
    float4*       Op = reinterpret_cast<float4*>(out)     + (size_t)b * seq * 256;
    const int*    mp = S_mas + (size_t)b * seq;

    const int row_end = (row0 + ROWS_PER_BLOCK < seq) ? row0 + ROWS_PER_BLOCK : seq;

    int r = row0;
    for (; r + UNROLL <= row_end; r += UNROLL) {
        float4 s[UNROLL];
        int    m[UNROLL];
#pragma unroll
        for (int u = 0; u < UNROLL; u++) {
            s[u] = __ldcs(&Sp[(size_t)(r + u) * 256 + tid]);
            m[u] = mp[r + u];
        }
#pragma unroll
        for (int u = 0; u < UNROLL; u++) {
            float p = s[u].x * w.x + s[u].y * w.y + s[u].z * w.z + s[u].w * w.w;
            p += __shfl_xor_sync(0xffffffffu, p, 8, 16);
            p += __shfl_xor_sync(0xffffffffu, p, 4, 16);
            p += __shfl_xor_sync(0xffffffffu, p, 2, 16);
            p += __shfl_xor_sync(0xffffffffu, p, 1, 16);
            const float beta = (p + c) * (m[u] != 0 ? 1.0f : 0.0f);
            float4 o;
            o.x = rv.x * beta;
            o.y = rv.y * beta;
            o.z = rv.z * beta;
            o.w = rv.w * beta;
            __stcs(&Op[(size_t)(r + u) * 256 + tid], o);
        }
    }
    for (; r < row_end; r++) {
        float4 s = __ldcs(&Sp[(size_t)r * 256 + tid]);
        int    m = mp[r];
        float p = s.x * w.x + s.y * w.y + s.z * w.z + s.w * w.w;
        p += __shfl_xor_sync(0xffffffffu, p, 8, 16);
        p += __shfl_xor_sync(0xffffffffu, p, 4, 16);
        p += __shfl_xor_sync(0xffffffffu, p, 2, 16);
        p += __shfl_xor_sync(0xffffffffu, p, 1, 16);
        const float beta = (p + c) * (m != 0 ? 1.0f : 0.0f);
        float4 o;
        o.x = rv.x * beta;
        o.y = rv.y * beta;
        o.z = rv.z * beta;
        o.w = rv.w * beta;
        __stcs(&Op[(size_t)r * 256 + tid], o);
    }
}

// ---------------------------------------------------------------------------
// Launch. Inputs (metadata order):
//   0 S (dps,seq,1024) f32   1 R (dps,1,1024) f32
//   2 S_mas (dps,seq,1) i32  3 R_mas (dps,1,1) i32 (dead)
//   4 WQ_w  5 WQ_b  6 WK_w  7 WK_b  8 WV_w  9 WV_b
// ---------------------------------------------------------------------------
extern "C" void kernel_launch(void* const* d_in, const int* in_sizes, int n_in,
                              void* d_out, int out_size) {
    const float* S     = (const float*)d_in[0];
    const float* R     = (const float*)d_in[1];
    const int*   S_mas = (const int*)  d_in[2];
    const float* WQ_w  = (const float*)d_in[4];
    const float* WQ_b  = (const float*)d_in[5];
    const float* WK_w  = (const float*)d_in[6];
    const float* WK_b  = (const float*)d_in[7];
    const float* WV_w  = (const float*)d_in[8];
    const float* WV_b  = (const float*)d_in[9];
    float* out = (float*)d_out;

    int dps = in_sizes[1] / 1024;          // R element count = dps*1024
    if (dps > MAX_DPS) dps = MAX_DPS;
    int seq = in_sizes[0] / (dps * 1024);  // S element count = dps*seq*1024

    precompute_kernel<<<dps, 256>>>(R, WQ_w, WQ_b, WK_w, WK_b, WV_w, WV_b);

    constexpr int ROWS   = 64;
    constexpr int UNROLL = 4;
    int nblk = (seq + ROWS - 1) / ROWS;
    stream_kernel<ROWS, UNROLL><<<dim3(dps, nblk), 256>>>(S, S_mas, out, seq);
}

// round 6
// speedup vs baseline: 1.0952x; 1.0100x over previous
#include <cuda_runtime.h>

// ---------------------------------------------------------------------------
// Algebraic collapse of the reference:
//   beta[b,s,h] = dot(S[b,s,h*64:(h+1)*64], g_W[b,h,:]) + g_C[b,h]
//   out[b,s,h*64+e] = g_RV[b,h,e] * beta * (S_mas[b,s] != 0)
// where g_W[b,h,d] = sum_e WQ_w[e,d] * R_K[b,h,e],
//       g_C[b,h]   = sum_e WQ_b[e]   * R_K[b,h,e],
//       R_K[b,h,e] = WK_b[e] + sum_d R[b,h*64+d]*WK_w[e,d]
//       g_RV[b,h,e]= WV_b[e] + sum_d R[b,h*64+d]*WV_w[e,d]
// HBM-bound streaming: 512 MB traffic -> ~75-80 us achievable floor on GB300.
// ---------------------------------------------------------------------------

#define MAX_DPS 64

__device__ float g_W [MAX_DPS * 1024];
__device__ float g_RV[MAX_DPS * 1024];
__device__ float g_C [MAX_DPS * 16];

// ---------------------------------------------------------------------------
// Kernel 1: precompute. grid (dps, 4), block 256 — 4 heads per block,
// thread = (h_local = t>>6 [warp-uniform], e = t&63).
// Phases A/B: weight ROWS via float4 LDG (L2-hot, high MLP) + float4
// broadcast LDS of r. Phase C: weight COLUMNS -> perfectly coalesced LDG
// across lanes + broadcast LDS of rk. No weight smem at all.
// ---------------------------------------------------------------------------
__global__ __launch_bounds__(256) void precompute_kernel(
    const float* __restrict__ R,
    const float* __restrict__ WQ_w,
    const float* __restrict__ WQ_b,
    const float* __restrict__ WK_w,
    const float* __restrict__ WK_b,
    const float* __restrict__ WV_w,
    const float* __restrict__ WV_b) {
    const int b  = blockIdx.x;
    const int hb = blockIdx.y;        // head-group: heads hb*4 .. hb*4+3
    const int t  = threadIdx.x;       // 0..255
    const int hl = t >> 6;            // 0..3, warp-uniform
    const int e  = t & 63;

    __shared__ float r_s [256];       // 4 heads x 64
    __shared__ float rk_s[256];

    r_s[t] = R[b * 1024 + hb * 256 + t];
    __syncthreads();

    // ---- Phases A+B fused: R_K and R_V for (head hl, element e) ----
    {
        const float4* wk = reinterpret_cast<const float4*>(WK_w + e * 64);
        const float4* wv = reinterpret_cast<const float4*>(WV_w + e * 64);
        const float4* rr = reinterpret_cast<const float4*>(r_s + hl * 64);
        float rk = WK_b[e];
        float rv = WV_b[e];
#pragma unroll
        for (int j = 0; j < 16; j++) {
            const float4 r4 = rr[j];          // broadcast LDS.128
            const float4 a  = wk[j];          // LDG.128 (L2-hot)
            const float4 v  = wv[j];
            rk = fmaf(a.x, r4.x, rk); rk = fmaf(a.y, r4.y, rk);
            rk = fmaf(a.z, r4.z, rk); rk = fmaf(a.w, r4.w, rk);
            rv = fmaf(v.x, r4.x, rv); rv = fmaf(v.y, r4.y, rv);
            rv = fmaf(v.z, r4.z, rv); rv = fmaf(v.w, r4.w, rv);
        }
        rk_s[t] = rk;
        g_RV[b * 1024 + hb * 256 + t] = rv;   // coalesced
    }
    __syncthreads();

    // ---- Phase C: W[d] = sum_e WQ_w[e,d] * R_K[e]  (d = t&63) ----
    {
        const int d = e;
        float w = 0.0f;
#pragma unroll 16
        for (int e2 = 0; e2 < 64; e2++)       // coalesced LDG + broadcast LDS
            w = fmaf(WQ_w[e2 * 64 + d], rk_s[hl * 64 + e2], w);
        g_W[b * 1024 + hb * 256 + t] = w;     // coalesced
    }

    // ---- c[h] = sum_e WQ_b[e] * R_K[h,e] ----
    if (t < 4) {
        float c = 0.0f;
#pragma unroll 8
        for (int e2 = 0; e2 < 64; e2++)
            c = fmaf(WQ_b[e2], rk_s[t * 64 + e2], c);
        g_C[b * 16 + hb * 4 + t] = c;
    }
}

// ---------------------------------------------------------------------------
// Kernel 2: streaming pass. grid (dps, ceil(seq/ROWS)), block 256.
// Thread owns one float4 slice of the 1024-wide row; head = 16 lanes;
// dot reduced with shfl.xor width=16. Plain LDG/STG (cache hints regressed).
// ---------------------------------------------------------------------------
template <int ROWS_PER_BLOCK, int UNROLL>
__global__ __launch_bounds__(256) void stream_kernel(
    const float* __restrict__ S,
    const int*   __restrict__ S_mas,
    float*       __restrict__ out,
    int seq) {
    const int b   = blockIdx.x;
    const int tid = threadIdx.x;      // 0..255
    const int h   = tid >> 4;         // head = 16 consecutive lanes

    const float4 w  = reinterpret_cast<const float4*>(g_W  + b * 1024)[tid];
    const float4 rv = reinterpret_cast<const float4*>(g_RV + b * 1024)[tid];
    const float  c  = g_C[b * 16 + h];

    const int row0 = blockIdx.y * ROWS_PER_BLOCK;
    const float4* Sp = reinterpret_cast<const float4*>(S) + (size_t)b * seq * 256;
    float4*       Op = reinterpret_cast<float4*>(out)     + (size_t)b * seq * 256;
    const int*    mp = S_mas + (size_t)b * seq;

    const int row_end = (row0 + ROWS_PER_BLOCK < seq) ? row0 + ROWS_PER_BLOCK : seq;

    int r = row0;
    for (; r + UNROLL <= row_end; r += UNROLL) {
        float4 s[UNROLL];
        int    m[UNROLL];
#pragma unroll
        for (int u = 0; u < UNROLL; u++) {
            s[u] = Sp[(size_t)(r + u) * 256 + tid];
            m[u] = mp[r + u];
        }
#pragma unroll
        for (int u = 0; u < UNROLL; u++) {
            float p = s[u].x * w.x + s[u].y * w.y + s[u].z * w.z + s[u].w * w.w;
            p += __shfl_xor_sync(0xffffffffu, p, 8, 16);
            p += __shfl_xor_sync(0xffffffffu, p, 4, 16);
            p += __shfl_xor_sync(0xffffffffu, p, 2, 16);
            p += __shfl_xor_sync(0xffffffffu, p, 1, 16);
            const float beta = (p + c) * (m[u] != 0 ? 1.0f : 0.0f);
            float4 o;
            o.x = rv.x * beta;
            o.y = rv.y * beta;
            o.z = rv.z * beta;
            o.w = rv.w * beta;
            Op[(size_t)(r + u) * 256 + tid] = o;
        }
    }
    for (; r < row_end; r++) {
        float4 s = Sp[(size_t)r * 256 + tid];
        int    m = mp[r];
        float p = s.x * w.x + s.y * w.y + s.z * w.z + s.w * w.w;
        p += __shfl_xor_sync(0xffffffffu, p, 8, 16);
        p += __shfl_xor_sync(0xffffffffu, p, 4, 16);
        p += __shfl_xor_sync(0xffffffffu, p, 2, 16);
        p += __shfl_xor_sync(0xffffffffu, p, 1, 16);
        const float beta = (p + c) * (m != 0 ? 1.0f : 0.0f);
        float4 o;
        o.x = rv.x * beta;
        o.y = rv.y * beta;
        o.z = rv.z * beta;
        o.w = rv.w * beta;
        Op[(size_t)r * 256 + tid] = o;
    }
}

// ---------------------------------------------------------------------------
// Launch. Inputs (metadata order):
//   0 S (dps,seq,1024) f32   1 R (dps,1,1024) f32
//   2 S_mas (dps,seq,1) i32  3 R_mas (dps,1,1) i32 (dead)
//   4 WQ_w  5 WQ_b  6 WK_w  7 WK_b  8 WV_w  9 WV_b
// ---------------------------------------------------------------------------
extern "C" void kernel_launch(void* const* d_in, const int* in_sizes, int n_in,
                              void* d_out, int out_size) {
    const float* S     = (const float*)d_in[0];
    const float* R     = (const float*)d_in[1];
    const int*   S_mas = (const int*)  d_in[2];
    const float* WQ_w  = (const float*)d_in[4];
    const float* WQ_b  = (const float*)d_in[5];
    const float* WK_w  = (const float*)d_in[6];
    const float* WK_b  = (const float*)d_in[7];
    const float* WV_w  = (const float*)d_in[8];
    const float* WV_b  = (const float*)d_in[9];
    float* out = (float*)d_out;

    int dps = in_sizes[1] / 1024;          // R element count = dps*1024
    if (dps > MAX_DPS) dps = MAX_DPS;
    int seq = in_sizes[0] / (dps * 1024);  // S element count = dps*seq*1024

    precompute_kernel<<<dim3(dps, 4), 256>>>(R, WQ_w, WQ_b, WK_w, WK_b,
                                             WV_w, WV_b);

    constexpr int ROWS   = 64;
    constexpr int UNROLL = 4;
    int nblk = (seq + ROWS - 1) / ROWS;
    stream_kernel<ROWS, UNROLL><<<dim3(dps, nblk), 256>>>(S, S_mas, out, seq);
}